// round 16
// baseline (speedup 1.0000x reference)
#include <cuda_runtime.h>
#include <cuda_bf16.h>

typedef unsigned int u32;
typedef unsigned long long u64;

// Problem: B=2,S=2048,D=2048,H=16,HD=128,PAST=2048,SKV=4096
// out = concat(out[2,2048,2048], k[2,16,4096,128], v[2,16,4096,128]) fp32

#define SCALE 0.08838834764831845f

// ---------------- scratch (__device__ globals; no runtime allocation) --------
__device__ __nv_bfloat16 g_xh[8388608],   g_xl[8388608];           // x split
__device__ __nv_bfloat16 g_wh[12582912],  g_wl[12582912];          // qkv_w split
__device__ __nv_bfloat16 g_owh[4194304],  g_owl[4194304];          // out_w split
__device__ __nv_bfloat16 g_qh[8388608],   g_ql[8388608];           // q split
__device__ __nv_bfloat16 g_kh[16777216],  g_kl[16777216];          // k cache split
__device__ __nv_bfloat16 g_vth[16777216], g_vtl[16777216];         // v^T split
__device__ __nv_bfloat16 g_ath[8388608],  g_atl[8388608];          // attn split

// ---------------- helpers ----------------
__device__ __forceinline__ u32 smem_u32(const void* p) {
    u32 a;
    asm("{ .reg .u64 t; cvta.to.shared.u64 t, %1; cvt.u32.u64 %0, t; }" : "=r"(a) : "l"(p));
    return a;
}
__device__ __forceinline__ void cp_async16(u32 dst, const void* src) {
    asm volatile("cp.async.cg.shared.global [%0], [%1], 16;" :: "r"(dst), "l"(src));
}
__device__ __forceinline__ void cp_commit() {
    asm volatile("cp.async.commit_group;" ::: "memory");
}
__device__ __forceinline__ void cp_wait1() {
    asm volatile("cp.async.wait_group 1;" ::: "memory");
}
__device__ __forceinline__ void cp_wait3() {
    asm volatile("cp.async.wait_group 3;" ::: "memory");
}
__device__ __forceinline__ void mma16816(float* d, u32 a0, u32 a1, u32 a2, u32 a3,
                                         u32 b0, u32 b1) {
    asm volatile("mma.sync.aligned.m16n8k16.row.col.f32.bf16.bf16.f32 "
                 "{%0,%1,%2,%3},{%4,%5,%6,%7},{%8,%9},{%0,%1,%2,%3};"
                 : "+f"(d[0]), "+f"(d[1]), "+f"(d[2]), "+f"(d[3])
                 : "r"(a0), "r"(a1), "r"(a2), "r"(a3), "r"(b0), "r"(b1));
}
__device__ __forceinline__ void bsplit(float v, __nv_bfloat16& h, __nv_bfloat16& l) {
    h = __float2bfloat16_rn(v);
    l = __float2bfloat16_rn(v - __bfloat162float(h));
}
__device__ __forceinline__ u32 packbf(__nv_bfloat16 a, __nv_bfloat16 b) {
    __nv_bfloat162 t = __halves2bfloat162(a, b);
    return *reinterpret_cast<u32*>(&t);
}

// ---------------- mma.sync split-bf16 GEMM: C[m,n]=sum_k A[m,k]*B[n,k] ------
// CTA tile 128x128, BK=32, 8 warps (4x2), warp tile 32x64.
// 3-stage pipeline, fill(c+2) issued BEFORE compute(c).
#define MAT_BYTES 10240
#define STG_BYTES 40960

template <class Epi>
__global__ __launch_bounds__(256, 1) void gemm_mma(
    const __nv_bfloat16* __restrict__ Ah, const __nv_bfloat16* __restrict__ Al,
    const __nv_bfloat16* __restrict__ Bh, const __nv_bfloat16* __restrict__ Bl,
    int K, long long sA, long long sB, Epi epi)
{
    extern __shared__ __align__(16) char sm[];
    const int tid  = threadIdx.x;
    const int wid  = tid >> 5;
    const int lane = tid & 31;
    const int z    = blockIdx.z;
    const int m0   = blockIdx.y * 128;
    const int n0   = blockIdx.x * 128;
    Ah += z * sA; Al += z * sA; Bh += z * sB; Bl += z * sB;

    const u32 sb = smem_u32(sm);
    const int g  = lane >> 2;
    const int tq = lane & 3;
    const int wm = (wid & 3) * 32;
    const int wn = (wid >> 2) * 64;

    float acc[2][8][4];
    #pragma unroll
    for (int i = 0; i < 2; i++)
        #pragma unroll
        for (int j = 0; j < 8; j++)
            #pragma unroll
            for (int r = 0; r < 4; r++) acc[i][j][r] = 0.f;

    const int nch = K >> 5;

    auto fill = [&](int buf, int k0) {
        const u32 base = sb + buf * STG_BYTES;
        #pragma unroll
        for (int i = 0; i < 2; i++) {
            int id = tid + i * 256;
            int r  = id >> 2;
            int cc = id & 3;
            u32 doff = r * 80 + cc * 16;
            long long ae = (long long)(m0 + r) * K + k0 + cc * 8;
            long long be = (long long)(n0 + r) * K + k0 + cc * 8;
            cp_async16(base + doff,                 Ah + ae);
            cp_async16(base + MAT_BYTES + doff,     Al + ae);
            cp_async16(base + 2 * MAT_BYTES + doff, Bh + be);
            cp_async16(base + 3 * MAT_BYTES + doff, Bl + be);
        }
    };

    fill(0, 0);  cp_commit();
    fill(1, 32); cp_commit();

    for (int c = 0; c < nch; c++) {
        const int buf = c % 3;
        cp_wait1();                // group c retired (only c+1 may be pending)
        __syncthreads();           // all warps done computing chunk c-1
        if (c + 2 < nch) fill((c + 2) % 3, (c + 2) * 32);
        cp_commit();

        const u32* uAh = reinterpret_cast<const u32*>(sm + buf * STG_BYTES);
        const u32* uAl = uAh + 2560;
        const u32* uBh = uAh + 5120;
        const u32* uBl = uAh + 7680;

        #pragma unroll
        for (int ks = 0; ks < 2; ks++) {
            const int ko2 = ks * 8;
            u32 ahf[2][4], alf[2][4];
            #pragma unroll
            for (int mt = 0; mt < 2; mt++) {
                int r0 = (wm + mt * 16 + g) * 20 + ko2 + tq;
                int r8 = r0 + 8 * 20;
                ahf[mt][0] = uAh[r0];     ahf[mt][1] = uAh[r8];
                ahf[mt][2] = uAh[r0 + 4]; ahf[mt][3] = uAh[r8 + 4];
                alf[mt][0] = uAl[r0];     alf[mt][1] = uAl[r8];
                alf[mt][2] = uAl[r0 + 4]; alf[mt][3] = uAl[r8 + 4];
            }
            u32 bhf[8][2], blf[8][2];
            #pragma unroll
            for (int nt = 0; nt < 8; nt++) {
                int rn = (wn + nt * 8 + g) * 20 + ko2 + tq;
                bhf[nt][0] = uBh[rn]; bhf[nt][1] = uBh[rn + 4];
                blf[nt][0] = uBl[rn]; blf[nt][1] = uBl[rn + 4];
            }
            #pragma unroll
            for (int mt = 0; mt < 2; mt++)
                #pragma unroll
                for (int nt = 0; nt < 8; nt++) {
                    float* d = acc[mt][nt];
                    mma16816(d, ahf[mt][0], ahf[mt][1], ahf[mt][2], ahf[mt][3],
                             bhf[nt][0], bhf[nt][1]);
                    mma16816(d, ahf[mt][0], ahf[mt][1], ahf[mt][2], ahf[mt][3],
                             blf[nt][0], blf[nt][1]);
                    mma16816(d, alf[mt][0], alf[mt][1], alf[mt][2], alf[mt][3],
                             bhf[nt][0], bhf[nt][1]);
                }
        }
    }

    __syncthreads();
    float* stg = reinterpret_cast<float*>(sm);
    #pragma unroll
    for (int mt = 0; mt < 2; mt++)
        #pragma unroll
        for (int nt = 0; nt < 8; nt++) {
            int r0 = wm + mt * 16 + g;
            int c0 = wn + nt * 8 + 2 * tq;
            stg[r0 * 132 + c0]           = acc[mt][nt][0];
            stg[r0 * 132 + c0 + 1]       = acc[mt][nt][1];
            stg[(r0 + 8) * 132 + c0]     = acc[mt][nt][2];
            stg[(r0 + 8) * 132 + c0 + 1] = acc[mt][nt][3];
        }
    __syncthreads();
    #pragma unroll 4
    for (int idx = tid; idx < 128 * 128; idx += 256) {
        int r = idx >> 7, cc = idx & 127;
        epi(z, m0 + r, n0 + cc, stg[r * 132 + cc]);
    }
}

// ---------------- epilogues ----------------
struct EpiQKV {
    const float* __restrict__ bias; float* ko; float* vo;
    __device__ __forceinline__ void operator()(int, int m, int n, float val) const {
        val += bias[n];
        int b = m >> 11, s = m & 2047;
        int h = (n & 2047) >> 7, hd = n & 127;
        if (n < 2048) {
            long long o = (((long long)(b * 16 + h) * 2048) + s) * 128 + hd;
            __nv_bfloat16 hi, lo; bsplit(val, hi, lo);
            g_qh[o] = hi; g_ql[o] = lo;
        } else if (n < 4096) {
            long long o = (((long long)(b * 16 + h) * 4096) + 2048 + s) * 128 + hd;
            ko[o] = val;
            __nv_bfloat16 hi, lo; bsplit(val, hi, lo);
            g_kh[o] = hi; g_kl[o] = lo;
        } else {
            long long o = (((long long)(b * 16 + h) * 4096) + 2048 + s) * 128 + hd;
            vo[o] = val;
        }
    }
};
struct EpiProj {
    const float* __restrict__ bias; float* out;
    __device__ __forceinline__ void operator()(int, int m, int n, float val) const {
        out[(long long)m * 2048 + n] = val + bias[n];
    }
};

// ---------------- fused attention: scores + online softmax + PV -------------
// Per CTA: z = b*16+h, 128 q rows. 8 warps x 16 rows. kv chunks of 64.
// S and PV both split-3 (measured rel_err 2.2e-5 in this configuration).
// SMEM: K stages 2 x (hi 20480 + lo 20480) at 0; V stages at 81920. Total 163840.
__global__ __launch_bounds__(256, 1) void fused_attn(
    const __nv_bfloat16* __restrict__ qh, const __nv_bfloat16* __restrict__ ql,
    const __nv_bfloat16* __restrict__ kh, const __nv_bfloat16* __restrict__ kl,
    const __nv_bfloat16* __restrict__ vth, const __nv_bfloat16* __restrict__ vtl,
    __nv_bfloat16* __restrict__ ath, __nv_bfloat16* __restrict__ atl)
{
    extern __shared__ __align__(16) char sm[];
    const int tid  = threadIdx.x;
    const int wid  = tid >> 5;
    const int lane = tid & 31;
    const int g    = lane >> 2;
    const int tq   = lane & 3;
    const int z    = blockIdx.y;
    const int m0   = blockIdx.x * 128;
    const int wm   = wid * 16;
    const u32 sb   = smem_u32(sm);

    // ---- Q fragments, K(hd)=128 -> 8 ksteps, hi+lo (one-time GMEM loads) ----
    const u32* q32h = reinterpret_cast<const u32*>(qh) + ((long long)z * 2048 + m0 + wm) * 64;
    const u32* q32l = reinterpret_cast<const u32*>(ql) + ((long long)z * 2048 + m0 + wm) * 64;
    u32 qfh[8][4], qfl[8][4];
    #pragma unroll
    for (int ks = 0; ks < 8; ks++) {
        int c0 = g * 64 + ks * 8 + tq;
        int c1 = (g + 8) * 64 + ks * 8 + tq;
        qfh[ks][0] = q32h[c0];     qfh[ks][1] = q32h[c1];
        qfh[ks][2] = q32h[c0 + 4]; qfh[ks][3] = q32h[c1 + 4];
        qfl[ks][0] = q32l[c0];     qfl[ks][1] = q32l[c1];
        qfl[ks][2] = q32l[c0 + 4]; qfl[ks][3] = q32l[c1 + 4];
    }

    float o[16][4];
    #pragma unroll
    for (int i = 0; i < 16; i++)
        #pragma unroll
        for (int r = 0; r < 4; r++) o[i][r] = 0.f;
    float mr0 = -1e30f, mr1 = -1e30f, l0 = 0.f, l1 = 0.f;

    // fill K chunk j into stage s: 4 hd-chunks x [64 rows x 80B], hi+lo
    auto fillK = [&](int s, int j) {
        int r  = tid >> 2, c4 = tid & 3;
        u32 dst = sb + s * 40960 + c4 * 5120 + r * 80;
        const __nv_bfloat16* ph_ = kh + ((long long)z * 4096 + j * 64 + r) * 128 + c4 * 32;
        const __nv_bfloat16* pl_ = kl + ((long long)z * 4096 + j * 64 + r) * 128 + c4 * 32;
        #pragma unroll
        for (int seg = 0; seg < 4; seg++) {
            cp_async16(dst + seg * 16,         ph_ + seg * 8);
            cp_async16(dst + 20480 + seg * 16, pl_ + seg * 8);
        }
    };
    // fill V^T chunk j into stage s: 2 kv-chunks x [128 rows x 80B], hi+lo
    auto fillV = [&](int s, int j) {
        int hd = tid >> 1, c32 = tid & 1;
        u32 dst = sb + 81920 + s * 40960 + c32 * 10240 + hd * 80;
        const __nv_bfloat16* ph_ = vth + ((long long)z * 128 + hd) * 4096 + j * 64 + c32 * 32;
        const __nv_bfloat16* pl_ = vtl + ((long long)z * 128 + hd) * 4096 + j * 64 + c32 * 32;
        #pragma unroll
        for (int seg = 0; seg < 4; seg++) {
            cp_async16(dst + seg * 16,         ph_ + seg * 8);
            cp_async16(dst + 20480 + seg * 16, pl_ + seg * 8);
        }
    };

    fillK(0, 0); cp_commit();
    fillV(0, 0); cp_commit();
    fillK(1, 1); cp_commit();
    fillV(1, 1); cp_commit();

    for (int j = 0; j < 64; j++) {
        const int s = j & 1;
        cp_wait3();
        __syncthreads();

        // ---- S = Q K^T over this kv chunk (split-3) ----
        float sacc[8][4];
        #pragma unroll
        for (int nf = 0; nf < 8; nf++)
            #pragma unroll
            for (int r = 0; r < 4; r++) sacc[nf][r] = 0.f;

        const u32* Kh32 = reinterpret_cast<const u32*>(sm + s * 40960);
        const u32* Kl32 = reinterpret_cast<const u32*>(sm + s * 40960 + 20480);
        #pragma unroll
        for (int ks = 0; ks < 8; ks++) {
            const int cb = (ks >> 1) * 1280 + (ks & 1) * 8;
            #pragma unroll
            for (int nf = 0; nf < 8; nf++) {
                int rn = cb + (nf * 8 + g) * 20 + tq;
                u32 b0h = Kh32[rn], b1h = Kh32[rn + 4];
                u32 b0l = Kl32[rn], b1l = Kl32[rn + 4];
                float* d = sacc[nf];
                mma16816(d, qfh[ks][0], qfh[ks][1], qfh[ks][2], qfh[ks][3], b0h, b1h);
                mma16816(d, qfh[ks][0], qfh[ks][1], qfh[ks][2], qfh[ks][3], b0l, b1l);
                mma16816(d, qfl[ks][0], qfl[ks][1], qfl[ks][2], qfl[ks][3], b0h, b1h);
            }
        }

        // ---- online softmax (rows g and g+8 of this warp's 16-row block) ----
        float cm0 = -1e30f, cm1 = -1e30f;
        #pragma unroll
        for (int nf = 0; nf < 8; nf++) {
            sacc[nf][0] *= SCALE; sacc[nf][1] *= SCALE;
            sacc[nf][2] *= SCALE; sacc[nf][3] *= SCALE;
            cm0 = fmaxf(cm0, fmaxf(sacc[nf][0], sacc[nf][1]));
            cm1 = fmaxf(cm1, fmaxf(sacc[nf][2], sacc[nf][3]));
        }
        cm0 = fmaxf(cm0, __shfl_xor_sync(0xffffffffu, cm0, 1));
        cm0 = fmaxf(cm0, __shfl_xor_sync(0xffffffffu, cm0, 2));
        cm1 = fmaxf(cm1, __shfl_xor_sync(0xffffffffu, cm1, 1));
        cm1 = fmaxf(cm1, __shfl_xor_sync(0xffffffffu, cm1, 2));
        float nm0 = fmaxf(mr0, cm0), nm1 = fmaxf(mr1, cm1);
        float sc0 = __expf(mr0 - nm0), sc1 = __expf(mr1 - nm1);
        mr0 = nm0; mr1 = nm1;

        u32 pah[8][2], pal[8][2];
        float rs0 = 0.f, rs1 = 0.f;
        #pragma unroll
        for (int nf = 0; nf < 8; nf++) {
            float p0 = __expf(sacc[nf][0] - nm0);
            float p1 = __expf(sacc[nf][1] - nm0);
            float p2 = __expf(sacc[nf][2] - nm1);
            float p3 = __expf(sacc[nf][3] - nm1);
            rs0 += p0 + p1; rs1 += p2 + p3;
            __nv_bfloat16 h0, e0, h1, e1, h2, e2, h3, e3;
            bsplit(p0, h0, e0); bsplit(p1, h1, e1);
            bsplit(p2, h2, e2); bsplit(p3, h3, e3);
            pah[nf][0] = packbf(h0, h1); pah[nf][1] = packbf(h2, h3);
            pal[nf][0] = packbf(e0, e1); pal[nf][1] = packbf(e2, e3);
        }
        rs0 += __shfl_xor_sync(0xffffffffu, rs0, 1);
        rs0 += __shfl_xor_sync(0xffffffffu, rs0, 2);
        rs1 += __shfl_xor_sync(0xffffffffu, rs1, 1);
        rs1 += __shfl_xor_sync(0xffffffffu, rs1, 2);
        l0 = l0 * sc0 + rs0;
        l1 = l1 * sc1 + rs1;
        #pragma unroll
        for (int hf = 0; hf < 16; hf++) {
            o[hf][0] *= sc0; o[hf][1] *= sc0;
            o[hf][2] *= sc1; o[hf][3] *= sc1;
        }

        __syncthreads();
        if (j + 2 < 64) fillK(s, j + 2);
        cp_commit();

        cp_wait3();
        __syncthreads();

        // ---- O += P V (split-3) ----
        const u32* Vh32 = reinterpret_cast<const u32*>(sm + 81920 + s * 40960);
        const u32* Vl32 = Vh32 + 5120;
        #pragma unroll
        for (int kp = 0; kp < 4; kp++) {
            const u32 ah0 = pah[2 * kp][0],     ah1 = pah[2 * kp][1];
            const u32 ah2 = pah[2 * kp + 1][0], ah3 = pah[2 * kp + 1][1];
            const u32 al0 = pal[2 * kp][0],     al1 = pal[2 * kp][1];
            const u32 al2 = pal[2 * kp + 1][0], al3 = pal[2 * kp + 1][1];
            const int cb = (kp >> 1) * 2560 + (kp & 1) * 8;
            #pragma unroll
            for (int hf = 0; hf < 16; hf++) {
                int rn = cb + (hf * 8 + g) * 20 + tq;
                u32 b0h = Vh32[rn], b1h = Vh32[rn + 4];
                u32 b0l = Vl32[rn], b1l = Vl32[rn + 4];
                float* d = o[hf];
                mma16816(d, ah0, ah1, ah2, ah3, b0h, b1h);
                mma16816(d, ah0, ah1, ah2, ah3, b0l, b1l);
                mma16816(d, al0, al1, al2, al3, b0h, b1h);
            }
        }

        __syncthreads();
        if (j + 2 < 64) fillV(s, j + 2);
        cp_commit();
    }

    // ---- normalize + write attn (bf16 split) ----
    float i0 = 1.f / l0, i1 = 1.f / l1;
    int b = z >> 4, h = z & 15;
    int row0 = m0 + wm + g, row1 = row0 + 8;
    u32* oh32 = reinterpret_cast<u32*>(ath);
    u32* ol32 = reinterpret_cast<u32*>(atl);
    #pragma unroll
    for (int hf = 0; hf < 16; hf++) {
        int col = hf * 8 + 2 * tq;
        float v0 = o[hf][0] * i0, v1 = o[hf][1] * i0;
        float v2 = o[hf][2] * i1, v3 = o[hf][3] * i1;
        __nv_bfloat16 h0, e0, h1, e1, h2, e2, h3, e3;
        bsplit(v0, h0, e0); bsplit(v1, h1, e1);
        bsplit(v2, h2, e2); bsplit(v3, h3, e3);
        long long idx0 = (((long long)(b * 2048 + row0)) * 2048 + h * 128 + col) >> 1;
        long long idx1 = (((long long)(b * 2048 + row1)) * 2048 + h * 128 + col) >> 1;
        oh32[idx0] = packbf(h0, h1); ol32[idx0] = packbf(e0, e1);
        oh32[idx1] = packbf(h2, h3); ol32[idx1] = packbf(e2, e3);
    }
}

// ---------------- fp32 -> (bf16 hi, bf16 lo) ----------------
__global__ __launch_bounds__(256) void convert_pair(
    const float4* __restrict__ src, __nv_bfloat162* __restrict__ hi,
    __nv_bfloat162* __restrict__ lo)
{
    long long i = (long long)blockIdx.x * 256 + threadIdx.x;
    float4 v = src[i];
    __nv_bfloat16 h0, l0, h1, l1, h2, l2, h3, l3;
    bsplit(v.x, h0, l0); bsplit(v.y, h1, l1);
    bsplit(v.z, h2, l2); bsplit(v.w, h3, l3);
    hi[2 * i]     = __halves2bfloat162(h0, h1);
    hi[2 * i + 1] = __halves2bfloat162(h2, h3);
    lo[2 * i]     = __halves2bfloat162(l0, l1);
    lo[2 * i + 1] = __halves2bfloat162(l2, l3);
}

// ---------------- copy past kv into cache outputs (+ k bf16 split) ----------
__global__ __launch_bounds__(256) void copy_past_kernel(
    const float4* __restrict__ pk, const float4* __restrict__ pv,
    float4* __restrict__ ko, float4* __restrict__ vo)
{
    long long i = (long long)blockIdx.x * 256 + threadIdx.x;
    int r = (int)(i >> 5);
    int c = (int)(i & 31);
    int bh = r >> 11, s = r & 2047;
    long long d = ((long long)bh * 4096 + s) * 32 + c;
    float4 k4 = pk[i], v4 = pv[i];
    ko[d] = k4; vo[d] = v4;
    __nv_bfloat16 h0, l0, h1, l1, h2, l2, h3, l3;
    bsplit(k4.x, h0, l0); bsplit(k4.y, h1, l1);
    bsplit(k4.z, h2, l2); bsplit(k4.w, h3, l3);
    __nv_bfloat162* kh2 = reinterpret_cast<__nv_bfloat162*>(g_kh);
    __nv_bfloat162* kl2 = reinterpret_cast<__nv_bfloat162*>(g_kl);
    kh2[2 * d]     = __halves2bfloat162(h0, h1);
    kh2[2 * d + 1] = __halves2bfloat162(h2, h3);
    kl2[2 * d]     = __halves2bfloat162(l0, l1);
    kl2[2 * d + 1] = __halves2bfloat162(l2, l3);
}

// ---------------- v [bh,skv,128] fp32 -> v^T [bh,128,skv] bf16 hi/lo --------
__global__ __launch_bounds__(256) void vtrans_kernel(const float* __restrict__ vo)
{
    __shared__ float tile[32][129];
    int bh = blockIdx.y;
    int s0 = blockIdx.x * 32;
    const float* src = vo + ((long long)bh * 4096 + s0) * 128;
    for (int i = threadIdx.x; i < 32 * 128; i += 256) {
        int s = i >> 7, hd = i & 127;
        tile[s][hd] = src[s * 128 + hd];
    }
    __syncthreads();
    for (int i = threadIdx.x; i < 128 * 32; i += 256) {
        int hd = i >> 5, s = i & 31;
        float v = tile[s][hd];
        __nv_bfloat16 hi, lo; bsplit(v, hi, lo);
        long long o = ((long long)bh * 128 + hd) * 4096 + s0 + s;
        g_vth[o] = hi; g_vtl[o] = lo;
    }
}

// ---------------- launch ----------------
extern "C" void kernel_launch(void* const* d_in, const int* in_sizes, int n_in,
                              void* d_out, int out_size)
{
    const float* x      = (const float*)d_in[0];
    const float* past_k = (const float*)d_in[1];
    const float* past_v = (const float*)d_in[2];
    const float* qkv_b  = (const float*)d_in[4];
    const float* out_b  = (const float*)d_in[6];

    float* out = (float*)d_out;
    float* ko  = out + 2LL * 2048 * 2048;
    float* vo  = ko + 2LL * 16 * 4096 * 128;

    #define SYM(p, s) void* p; cudaGetSymbolAddress(&p, s)
    SYM(p_xh, g_xh);  SYM(p_xl, g_xl);
    SYM(p_wh, g_wh);  SYM(p_wl, g_wl);
    SYM(p_owh, g_owh); SYM(p_owl, g_owl);
    SYM(p_qh, g_qh);  SYM(p_ql, g_ql);
    SYM(p_kh, g_kh);  SYM(p_kl, g_kl);
    SYM(p_vth, g_vth); SYM(p_vtl, g_vtl);
    SYM(p_ath, g_ath); SYM(p_atl, g_atl);
    #undef SYM

    const int SMEM = 3 * STG_BYTES;      // 122880 for gemm_mma (3-stage)
    const int SMEM_FA = 163840;          // fused attn: K 2x40960 + V 2x40960
    cudaFuncSetAttribute(gemm_mma<EpiQKV>,  cudaFuncAttributeMaxDynamicSharedMemorySize, SMEM);
    cudaFuncSetAttribute(gemm_mma<EpiProj>, cudaFuncAttributeMaxDynamicSharedMemorySize, SMEM);
    cudaFuncSetAttribute(fused_attn,        cudaFuncAttributeMaxDynamicSharedMemorySize, SMEM_FA);

    // 1) input splits
    convert_pair<<<8192, 256>>>((const float4*)x,
        (__nv_bfloat162*)p_xh, (__nv_bfloat162*)p_xl);
    convert_pair<<<12288, 256>>>((const float4*)d_in[3],
        (__nv_bfloat162*)p_wh, (__nv_bfloat162*)p_wl);
    convert_pair<<<4096, 256>>>((const float4*)d_in[5],
        (__nv_bfloat162*)p_owh, (__nv_bfloat162*)p_owl);

    // 2) past kv -> cache outputs (+ k bf16 split)
    copy_past_kernel<<<8192, 256>>>((const float4*)past_k, (const float4*)past_v,
                                    (float4*)ko, (float4*)vo);

    // 3) QKV projection
    {
        EpiQKV epi{qkv_b, ko, vo};
        gemm_mma<EpiQKV><<<dim3(48, 32, 1), 256, SMEM>>>(
            (const __nv_bfloat16*)p_xh, (const __nv_bfloat16*)p_xl,
            (const __nv_bfloat16*)p_wh, (const __nv_bfloat16*)p_wl,
            2048, 0LL, 0LL, epi);
    }

    // 4) v -> v^T bf16 split (full cache)
    vtrans_kernel<<<dim3(128, 32), 256>>>(vo);

    // 5) fused attention: scores + softmax + PV -> attn bf16 split
    fused_attn<<<dim3(16, 32), 256, SMEM_FA>>>(
        (const __nv_bfloat16*)p_qh, (const __nv_bfloat16*)p_ql,
        (const __nv_bfloat16*)p_kh, (const __nv_bfloat16*)p_kl,
        (const __nv_bfloat16*)p_vth, (const __nv_bfloat16*)p_vtl,
        (__nv_bfloat16*)p_ath, (__nv_bfloat16*)p_atl);

    // 6) output projection
    {
        EpiProj epi{out_b, out};
        gemm_mma<EpiProj><<<dim3(16, 32, 1), 256, SMEM>>>(
            (const __nv_bfloat16*)p_ath, (const __nv_bfloat16*)p_atl,
            (const __nv_bfloat16*)p_owh, (const __nv_bfloat16*)p_owl,
            2048, 0LL, 0LL, epi);
    }
}

// round 17
// speedup vs baseline: 1.2233x; 1.2233x over previous
#include <cuda_runtime.h>
#include <cuda_bf16.h>
#include <cuda_fp16.h>

typedef unsigned int u32;
typedef unsigned long long u64;

// Problem: B=2,S=2048,D=2048,H=16,HD=128,PAST=2048,SKV=4096
// out = concat(out[2,2048,2048], k[2,16,4096,128], v[2,16,4096,128]) fp32

#define SCALE 0.08838834764831845f

// ---------------- scratch (__device__ globals; no runtime allocation) --------
__device__ __nv_bfloat16 g_xh[8388608],   g_xl[8388608];           // x split (bf16, GEMM)
__device__ __nv_bfloat16 g_wh[12582912],  g_wl[12582912];          // qkv_w split
__device__ __nv_bfloat16 g_owh[4194304],  g_owl[4194304];          // out_w split
__device__ __nv_bfloat16 g_ath[8388608],  g_atl[8388608];          // attn split (bf16, proj in)
__device__ __half g_qf[8388608];                                   // q fp16 (fused)
__device__ __half g_kf[16777216];                                  // k cache fp16 (fused)
__device__ __half g_vfh[16777216], g_vfl[16777216];                // v^T fp16 split (fused)

// ---------------- helpers ----------------
__device__ __forceinline__ u32 smem_u32(const void* p) {
    u32 a;
    asm("{ .reg .u64 t; cvta.to.shared.u64 t, %1; cvt.u32.u64 %0, t; }" : "=r"(a) : "l"(p));
    return a;
}
__device__ __forceinline__ void cp_async16(u32 dst, const void* src) {
    asm volatile("cp.async.cg.shared.global [%0], [%1], 16;" :: "r"(dst), "l"(src));
}
__device__ __forceinline__ void cp_commit() {
    asm volatile("cp.async.commit_group;" ::: "memory");
}
__device__ __forceinline__ void cp_wait1() {
    asm volatile("cp.async.wait_group 1;" ::: "memory");
}
__device__ __forceinline__ void cp_wait3() {
    asm volatile("cp.async.wait_group 3;" ::: "memory");
}
// bf16 mma (QKV / proj GEMMs)
__device__ __forceinline__ void mma16816(float* d, u32 a0, u32 a1, u32 a2, u32 a3,
                                         u32 b0, u32 b1) {
    asm volatile("mma.sync.aligned.m16n8k16.row.col.f32.bf16.bf16.f32 "
                 "{%0,%1,%2,%3},{%4,%5,%6,%7},{%8,%9},{%0,%1,%2,%3};"
                 : "+f"(d[0]), "+f"(d[1]), "+f"(d[2]), "+f"(d[3])
                 : "r"(a0), "r"(a1), "r"(a2), "r"(a3), "r"(b0), "r"(b1));
}
// fp16 mma (fused attention)
__device__ __forceinline__ void mma16816h(float* d, u32 a0, u32 a1, u32 a2, u32 a3,
                                          u32 b0, u32 b1) {
    asm volatile("mma.sync.aligned.m16n8k16.row.col.f32.f16.f16.f32 "
                 "{%0,%1,%2,%3},{%4,%5,%6,%7},{%8,%9},{%0,%1,%2,%3};"
                 : "+f"(d[0]), "+f"(d[1]), "+f"(d[2]), "+f"(d[3])
                 : "r"(a0), "r"(a1), "r"(a2), "r"(a3), "r"(b0), "r"(b1));
}
__device__ __forceinline__ void bsplit(float v, __nv_bfloat16& h, __nv_bfloat16& l) {
    h = __float2bfloat16_rn(v);
    l = __float2bfloat16_rn(v - __bfloat162float(h));
}
__device__ __forceinline__ void hsplit(float v, __half& h, __half& l) {
    h = __float2half_rn(v);
    l = __float2half_rn(v - __half2float(h));
}
__device__ __forceinline__ u32 packbf(__nv_bfloat16 a, __nv_bfloat16 b) {
    __nv_bfloat162 t = __halves2bfloat162(a, b);
    return *reinterpret_cast<u32*>(&t);
}
__device__ __forceinline__ u32 packh(__half a, __half b) {
    __half2 t = __halves2half2(a, b);
    return *reinterpret_cast<u32*>(&t);
}

// ---------------- mma.sync split-bf16 GEMM: C[m,n]=sum_k A[m,k]*B[n,k] ------
// CTA tile 128x128, BK=32, 8 warps (4x2), warp tile 32x64. 3-stage pipeline.
#define MAT_BYTES 10240
#define STG_BYTES 40960

template <class Epi>
__global__ __launch_bounds__(256, 1) void gemm_mma(
    const __nv_bfloat16* __restrict__ Ah, const __nv_bfloat16* __restrict__ Al,
    const __nv_bfloat16* __restrict__ Bh, const __nv_bfloat16* __restrict__ Bl,
    int K, long long sA, long long sB, Epi epi)
{
    extern __shared__ __align__(16) char sm[];
    const int tid  = threadIdx.x;
    const int wid  = tid >> 5;
    const int lane = tid & 31;
    const int z    = blockIdx.z;
    const int m0   = blockIdx.y * 128;
    const int n0   = blockIdx.x * 128;
    Ah += z * sA; Al += z * sA; Bh += z * sB; Bl += z * sB;

    const u32 sb = smem_u32(sm);
    const int g  = lane >> 2;
    const int tq = lane & 3;
    const int wm = (wid & 3) * 32;
    const int wn = (wid >> 2) * 64;

    float acc[2][8][4];
    #pragma unroll
    for (int i = 0; i < 2; i++)
        #pragma unroll
        for (int j = 0; j < 8; j++)
            #pragma unroll
            for (int r = 0; r < 4; r++) acc[i][j][r] = 0.f;

    const int nch = K >> 5;

    auto fill = [&](int buf, int k0) {
        const u32 base = sb + buf * STG_BYTES;
        #pragma unroll
        for (int i = 0; i < 2; i++) {
            int id = tid + i * 256;
            int r  = id >> 2;
            int cc = id & 3;
            u32 doff = r * 80 + cc * 16;
            long long ae = (long long)(m0 + r) * K + k0 + cc * 8;
            long long be = (long long)(n0 + r) * K + k0 + cc * 8;
            cp_async16(base + doff,                 Ah + ae);
            cp_async16(base + MAT_BYTES + doff,     Al + ae);
            cp_async16(base + 2 * MAT_BYTES + doff, Bh + be);
            cp_async16(base + 3 * MAT_BYTES + doff, Bl + be);
        }
    };

    fill(0, 0);  cp_commit();
    fill(1, 32); cp_commit();

    for (int c = 0; c < nch; c++) {
        const int buf = c % 3;
        cp_wait1();
        __syncthreads();
        if (c + 2 < nch) fill((c + 2) % 3, (c + 2) * 32);
        cp_commit();

        const u32* uAh = reinterpret_cast<const u32*>(sm + buf * STG_BYTES);
        const u32* uAl = uAh + 2560;
        const u32* uBh = uAh + 5120;
        const u32* uBl = uAh + 7680;

        #pragma unroll
        for (int ks = 0; ks < 2; ks++) {
            const int ko2 = ks * 8;
            u32 ahf[2][4], alf[2][4];
            #pragma unroll
            for (int mt = 0; mt < 2; mt++) {
                int r0 = (wm + mt * 16 + g) * 20 + ko2 + tq;
                int r8 = r0 + 8 * 20;
                ahf[mt][0] = uAh[r0];     ahf[mt][1] = uAh[r8];
                ahf[mt][2] = uAh[r0 + 4]; ahf[mt][3] = uAh[r8 + 4];
                alf[mt][0] = uAl[r0];     alf[mt][1] = uAl[r8];
                alf[mt][2] = uAl[r0 + 4]; alf[mt][3] = uAl[r8 + 4];
            }
            u32 bhf[8][2], blf[8][2];
            #pragma unroll
            for (int nt = 0; nt < 8; nt++) {
                int rn = (wn + nt * 8 + g) * 20 + ko2 + tq;
                bhf[nt][0] = uBh[rn]; bhf[nt][1] = uBh[rn + 4];
                blf[nt][0] = uBl[rn]; blf[nt][1] = uBl[rn + 4];
            }
            #pragma unroll
            for (int mt = 0; mt < 2; mt++)
                #pragma unroll
                for (int nt = 0; nt < 8; nt++) {
                    float* d = acc[mt][nt];
                    mma16816(d, ahf[mt][0], ahf[mt][1], ahf[mt][2], ahf[mt][3],
                             bhf[nt][0], bhf[nt][1]);
                    mma16816(d, ahf[mt][0], ahf[mt][1], ahf[mt][2], ahf[mt][3],
                             blf[nt][0], blf[nt][1]);
                    mma16816(d, alf[mt][0], alf[mt][1], alf[mt][2], alf[mt][3],
                             bhf[nt][0], bhf[nt][1]);
                }
        }
    }

    __syncthreads();
    float* stg = reinterpret_cast<float*>(sm);
    #pragma unroll
    for (int mt = 0; mt < 2; mt++)
        #pragma unroll
        for (int nt = 0; nt < 8; nt++) {
            int r0 = wm + mt * 16 + g;
            int c0 = wn + nt * 8 + 2 * tq;
            stg[r0 * 132 + c0]           = acc[mt][nt][0];
            stg[r0 * 132 + c0 + 1]       = acc[mt][nt][1];
            stg[(r0 + 8) * 132 + c0]     = acc[mt][nt][2];
            stg[(r0 + 8) * 132 + c0 + 1] = acc[mt][nt][3];
        }
    __syncthreads();
    #pragma unroll 4
    for (int idx = tid; idx < 128 * 128; idx += 256) {
        int r = idx >> 7, cc = idx & 127;
        epi(z, m0 + r, n0 + cc, stg[r * 132 + cc]);
    }
}

// ---------------- epilogues ----------------
struct EpiQKV {
    const float* __restrict__ bias; float* ko; float* vo;
    __device__ __forceinline__ void operator()(int, int m, int n, float val) const {
        val += bias[n];
        int b = m >> 11, s = m & 2047;
        int h = (n & 2047) >> 7, hd = n & 127;
        if (n < 2048) {
            long long o = (((long long)(b * 16 + h) * 2048) + s) * 128 + hd;
            g_qf[o] = __float2half_rn(val);
        } else if (n < 4096) {
            long long o = (((long long)(b * 16 + h) * 4096) + 2048 + s) * 128 + hd;
            ko[o] = val;
            g_kf[o] = __float2half_rn(val);
        } else {
            long long o = (((long long)(b * 16 + h) * 4096) + 2048 + s) * 128 + hd;
            vo[o] = val;
        }
    }
};
struct EpiProj {
    const float* __restrict__ bias; float* out;
    __device__ __forceinline__ void operator()(int, int m, int n, float val) const {
        out[(long long)m * 2048 + n] = val + bias[n];
    }
};

// ---------------- fused attention (fp16): S single, P single x V split-2 ----
// Per CTA: z = b*16+h, 128 q rows. 8 warps x 16 rows. kv chunks of 64.
// SMEM: K stages 2x20480 at 0; V stages 2x40960 (hi+lo) at 40960. Total 122880.
__global__ __launch_bounds__(256, 1) void fused_attn(
    const __half* __restrict__ qf,
    const __half* __restrict__ kf,
    const __half* __restrict__ vfh, const __half* __restrict__ vfl,
    __nv_bfloat16* __restrict__ ath, __nv_bfloat16* __restrict__ atl)
{
    extern __shared__ __align__(16) char sm[];
    const int tid  = threadIdx.x;
    const int wid  = tid >> 5;
    const int lane = tid & 31;
    const int g    = lane >> 2;
    const int tq   = lane & 3;
    const int z    = blockIdx.y;
    const int m0   = blockIdx.x * 128;
    const int wm   = wid * 16;
    const u32 sb   = smem_u32(sm);

    // ---- Q fp16 fragments, hd=128 -> 8 ksteps ----
    const u32* q32 = reinterpret_cast<const u32*>(qf) + ((long long)z * 2048 + m0 + wm) * 64;
    u32 qfr[8][4];
    #pragma unroll
    for (int ks = 0; ks < 8; ks++) {
        int c0 = g * 64 + ks * 8 + tq;
        int c1 = (g + 8) * 64 + ks * 8 + tq;
        qfr[ks][0] = q32[c0];     qfr[ks][1] = q32[c1];
        qfr[ks][2] = q32[c0 + 4]; qfr[ks][3] = q32[c1 + 4];
    }

    float o[16][4];
    #pragma unroll
    for (int i = 0; i < 16; i++)
        #pragma unroll
        for (int r = 0; r < 4; r++) o[i][r] = 0.f;
    float mr0 = -1e30f, mr1 = -1e30f, l0 = 0.f, l1 = 0.f;

    // fill K chunk j (fp16 single) into stage s: 4 hd-chunks x [64 rows x 80B]
    auto fillK = [&](int s, int j) {
        int r  = tid >> 2, c4 = tid & 3;
        u32 dst = sb + s * 20480 + c4 * 5120 + r * 80;
        const __half* p_ = kf + ((long long)z * 4096 + j * 64 + r) * 128 + c4 * 32;
        #pragma unroll
        for (int seg = 0; seg < 4; seg++)
            cp_async16(dst + seg * 16, p_ + seg * 8);
    };
    // fill V^T chunk j (fp16 hi+lo) into stage s: 2 kv-chunks x [128 rows x 80B]
    auto fillV = [&](int s, int j) {
        int hd = tid >> 1, c32 = tid & 1;
        u32 dst = sb + 40960 + s * 40960 + c32 * 10240 + hd * 80;
        const __half* ph_ = vfh + ((long long)z * 128 + hd) * 4096 + j * 64 + c32 * 32;
        const __half* pl_ = vfl + ((long long)z * 128 + hd) * 4096 + j * 64 + c32 * 32;
        #pragma unroll
        for (int seg = 0; seg < 4; seg++) {
            cp_async16(dst + seg * 16,         ph_ + seg * 8);
            cp_async16(dst + 20480 + seg * 16, pl_ + seg * 8);
        }
    };

    fillK(0, 0); cp_commit();
    fillV(0, 0); cp_commit();
    fillK(1, 1); cp_commit();
    fillV(1, 1); cp_commit();

    for (int j = 0; j < 64; j++) {
        const int s = j & 1;
        cp_wait3();
        __syncthreads();

        // ---- S = Q K^T (single fp16) ----
        float sacc[8][4];
        #pragma unroll
        for (int nf = 0; nf < 8; nf++)
            #pragma unroll
            for (int r = 0; r < 4; r++) sacc[nf][r] = 0.f;

        const u32* K32 = reinterpret_cast<const u32*>(sm + s * 20480);
        #pragma unroll
        for (int ks = 0; ks < 8; ks++) {
            const int cb = (ks >> 1) * 1280 + (ks & 1) * 8;
            #pragma unroll
            for (int nf = 0; nf < 8; nf++) {
                int rn = cb + (nf * 8 + g) * 20 + tq;
                mma16816h(sacc[nf], qfr[ks][0], qfr[ks][1], qfr[ks][2], qfr[ks][3],
                          K32[rn], K32[rn + 4]);
            }
        }

        // ---- online softmax ----
        float cm0 = -1e30f, cm1 = -1e30f;
        #pragma unroll
        for (int nf = 0; nf < 8; nf++) {
            sacc[nf][0] *= SCALE; sacc[nf][1] *= SCALE;
            sacc[nf][2] *= SCALE; sacc[nf][3] *= SCALE;
            cm0 = fmaxf(cm0, fmaxf(sacc[nf][0], sacc[nf][1]));
            cm1 = fmaxf(cm1, fmaxf(sacc[nf][2], sacc[nf][3]));
        }
        cm0 = fmaxf(cm0, __shfl_xor_sync(0xffffffffu, cm0, 1));
        cm0 = fmaxf(cm0, __shfl_xor_sync(0xffffffffu, cm0, 2));
        cm1 = fmaxf(cm1, __shfl_xor_sync(0xffffffffu, cm1, 1));
        cm1 = fmaxf(cm1, __shfl_xor_sync(0xffffffffu, cm1, 2));
        float nm0 = fmaxf(mr0, cm0), nm1 = fmaxf(mr1, cm1);
        float sc0 = __expf(mr0 - nm0), sc1 = __expf(mr1 - nm1);
        mr0 = nm0; mr1 = nm1;

        u32 pa[8][2];
        float rs0 = 0.f, rs1 = 0.f;
        #pragma unroll
        for (int nf = 0; nf < 8; nf++) {
            float p0 = __expf(sacc[nf][0] - nm0);
            float p1 = __expf(sacc[nf][1] - nm0);
            float p2 = __expf(sacc[nf][2] - nm1);
            float p3 = __expf(sacc[nf][3] - nm1);
            rs0 += p0 + p1; rs1 += p2 + p3;
            pa[nf][0] = packh(__float2half_rn(p0), __float2half_rn(p1));
            pa[nf][1] = packh(__float2half_rn(p2), __float2half_rn(p3));
        }
        rs0 += __shfl_xor_sync(0xffffffffu, rs0, 1);
        rs0 += __shfl_xor_sync(0xffffffffu, rs0, 2);
        rs1 += __shfl_xor_sync(0xffffffffu, rs1, 1);
        rs1 += __shfl_xor_sync(0xffffffffu, rs1, 2);
        l0 = l0 * sc0 + rs0;
        l1 = l1 * sc1 + rs1;
        #pragma unroll
        for (int hf = 0; hf < 16; hf++) {
            o[hf][0] *= sc0; o[hf][1] *= sc0;
            o[hf][2] *= sc1; o[hf][3] *= sc1;
        }

        __syncthreads();
        if (j + 2 < 64) fillK(s, j + 2);
        cp_commit();

        cp_wait3();
        __syncthreads();

        // ---- O += P (Vh + Vl) : 2 MMAs per tile ----
        const u32* Vh32 = reinterpret_cast<const u32*>(sm + 40960 + s * 40960);
        const u32* Vl32 = Vh32 + 5120;
        #pragma unroll
        for (int kp = 0; kp < 4; kp++) {
            const u32 a0 = pa[2 * kp][0],     a1 = pa[2 * kp][1];
            const u32 a2 = pa[2 * kp + 1][0], a3 = pa[2 * kp + 1][1];
            const int cb = (kp >> 1) * 2560 + (kp & 1) * 8;
            #pragma unroll
            for (int hf = 0; hf < 16; hf++) {
                int rn = cb + (hf * 8 + g) * 20 + tq;
                float* d = o[hf];
                mma16816h(d, a0, a1, a2, a3, Vh32[rn], Vh32[rn + 4]);
                mma16816h(d, a0, a1, a2, a3, Vl32[rn], Vl32[rn + 4]);
            }
        }

        __syncthreads();
        if (j + 2 < 64) fillV(s, j + 2);
        cp_commit();
    }

    // ---- normalize + write attn (bf16 split for proj GEMM) ----
    float i0 = 1.f / l0, i1 = 1.f / l1;
    int b = z >> 4, h = z & 15;
    int row0 = m0 + wm + g, row1 = row0 + 8;
    u32* oh32 = reinterpret_cast<u32*>(ath);
    u32* ol32 = reinterpret_cast<u32*>(atl);
    #pragma unroll
    for (int hf = 0; hf < 16; hf++) {
        int col = hf * 8 + 2 * tq;
        float v0 = o[hf][0] * i0, v1 = o[hf][1] * i0;
        float v2 = o[hf][2] * i1, v3 = o[hf][3] * i1;
        __nv_bfloat16 h0, e0, h1, e1, h2, e2, h3, e3;
        bsplit(v0, h0, e0); bsplit(v1, h1, e1);
        bsplit(v2, h2, e2); bsplit(v3, h3, e3);
        long long idx0 = (((long long)(b * 2048 + row0)) * 2048 + h * 128 + col) >> 1;
        long long idx1 = (((long long)(b * 2048 + row1)) * 2048 + h * 128 + col) >> 1;
        oh32[idx0] = packbf(h0, h1); ol32[idx0] = packbf(e0, e1);
        oh32[idx1] = packbf(h2, h3); ol32[idx1] = packbf(e2, e3);
    }
}

// ---------------- fp32 -> (bf16 hi, bf16 lo) ----------------
__global__ __launch_bounds__(256) void convert_pair(
    const float4* __restrict__ src, __nv_bfloat162* __restrict__ hi,
    __nv_bfloat162* __restrict__ lo)
{
    long long i = (long long)blockIdx.x * 256 + threadIdx.x;
    float4 v = src[i];
    __nv_bfloat16 h0, l0, h1, l1, h2, l2, h3, l3;
    bsplit(v.x, h0, l0); bsplit(v.y, h1, l1);
    bsplit(v.z, h2, l2); bsplit(v.w, h3, l3);
    hi[2 * i]     = __halves2bfloat162(h0, h1);
    hi[2 * i + 1] = __halves2bfloat162(h2, h3);
    lo[2 * i]     = __halves2bfloat162(l0, l1);
    lo[2 * i + 1] = __halves2bfloat162(l2, l3);
}

// ---------------- copy past kv into cache outputs (+ k fp16) ----------------
__global__ __launch_bounds__(256) void copy_past_kernel(
    const float4* __restrict__ pk, const float4* __restrict__ pv,
    float4* __restrict__ ko, float4* __restrict__ vo)
{
    long long i = (long long)blockIdx.x * 256 + threadIdx.x;
    int r = (int)(i >> 5);
    int c = (int)(i & 31);
    int bh = r >> 11, s = r & 2047;
    long long d = ((long long)bh * 4096 + s) * 32 + c;
    float4 k4 = pk[i], v4 = pv[i];
    ko[d] = k4; vo[d] = v4;
    __half2* kf2 = reinterpret_cast<__half2*>(g_kf);
    kf2[2 * d]     = __halves2half2(__float2half_rn(k4.x), __float2half_rn(k4.y));
    kf2[2 * d + 1] = __halves2half2(__float2half_rn(k4.z), __float2half_rn(k4.w));
}

// ---------------- v [bh,skv,128] fp32 -> v^T [bh,128,skv] fp16 hi/lo --------
__global__ __launch_bounds__(256) void vtrans_kernel(const float* __restrict__ vo)
{
    __shared__ float tile[32][129];
    int bh = blockIdx.y;
    int s0 = blockIdx.x * 32;
    const float* src = vo + ((long long)bh * 4096 + s0) * 128;
    for (int i = threadIdx.x; i < 32 * 128; i += 256) {
        int s = i >> 7, hd = i & 127;
        tile[s][hd] = src[s * 128 + hd];
    }
    __syncthreads();
    for (int i = threadIdx.x; i < 128 * 32; i += 256) {
        int hd = i >> 5, s = i & 31;
        float v = tile[s][hd];
        __half hi, lo; hsplit(v, hi, lo);
        long long o = ((long long)bh * 128 + hd) * 4096 + s0 + s;
        g_vfh[o] = hi; g_vfl[o] = lo;
    }
}

// ---------------- launch ----------------
extern "C" void kernel_launch(void* const* d_in, const int* in_sizes, int n_in,
                              void* d_out, int out_size)
{
    const float* x      = (const float*)d_in[0];
    const float* past_k = (const float*)d_in[1];
    const float* past_v = (const float*)d_in[2];
    const float* qkv_b  = (const float*)d_in[4];
    const float* out_b  = (const float*)d_in[6];

    float* out = (float*)d_out;
    float* ko  = out + 2LL * 2048 * 2048;
    float* vo  = ko + 2LL * 16 * 4096 * 128;

    #define SYM(p, s) void* p; cudaGetSymbolAddress(&p, s)
    SYM(p_xh, g_xh);  SYM(p_xl, g_xl);
    SYM(p_wh, g_wh);  SYM(p_wl, g_wl);
    SYM(p_owh, g_owh); SYM(p_owl, g_owl);
    SYM(p_qf, g_qf);
    SYM(p_kf, g_kf);
    SYM(p_vfh, g_vfh); SYM(p_vfl, g_vfl);
    SYM(p_ath, g_ath); SYM(p_atl, g_atl);
    #undef SYM

    const int SMEM = 3 * STG_BYTES;      // 122880 for gemm_mma (3-stage)
    const int SMEM_FA = 122880;          // fused attn: K 2x20480 + V 2x40960
    cudaFuncSetAttribute(gemm_mma<EpiQKV>,  cudaFuncAttributeMaxDynamicSharedMemorySize, SMEM);
    cudaFuncSetAttribute(gemm_mma<EpiProj>, cudaFuncAttributeMaxDynamicSharedMemorySize, SMEM);
    cudaFuncSetAttribute(fused_attn,        cudaFuncAttributeMaxDynamicSharedMemorySize, SMEM_FA);

    // 1) input splits (bf16, GEMM path)
    convert_pair<<<8192, 256>>>((const float4*)x,
        (__nv_bfloat162*)p_xh, (__nv_bfloat162*)p_xl);
    convert_pair<<<12288, 256>>>((const float4*)d_in[3],
        (__nv_bfloat162*)p_wh, (__nv_bfloat162*)p_wl);
    convert_pair<<<4096, 256>>>((const float4*)d_in[5],
        (__nv_bfloat162*)p_owh, (__nv_bfloat162*)p_owl);

    // 2) past kv -> cache outputs (+ k fp16)
    copy_past_kernel<<<8192, 256>>>((const float4*)past_k, (const float4*)past_v,
                                    (float4*)ko, (float4*)vo);

    // 3) QKV projection (bf16 split-3)
    {
        EpiQKV epi{qkv_b, ko, vo};
        gemm_mma<EpiQKV><<<dim3(48, 32, 1), 256, SMEM>>>(
            (const __nv_bfloat16*)p_xh, (const __nv_bfloat16*)p_xl,
            (const __nv_bfloat16*)p_wh, (const __nv_bfloat16*)p_wl,
            2048, 0LL, 0LL, epi);
    }

    // 4) v -> v^T fp16 split (full cache)
    vtrans_kernel<<<dim3(128, 32), 256>>>(vo);

    // 5) fused attention (fp16): scores + softmax + PV -> attn bf16 split
    fused_attn<<<dim3(16, 32), 256, SMEM_FA>>>(
        (const __half*)p_qf,
        (const __half*)p_kf,
        (const __half*)p_vfh, (const __half*)p_vfl,
        (__nv_bfloat16*)p_ath, (__nv_bfloat16*)p_atl);

    // 6) output projection (bf16 split-3)
    {
        EpiProj epi{out_b, out};
        gemm_mma<EpiProj><<<dim3(16, 32, 1), 256, SMEM>>>(
            (const __nv_bfloat16*)p_ath, (const __nv_bfloat16*)p_atl,
            (const __nv_bfloat16*)p_owh, (const __nv_bfloat16*)p_owl,
            2048, 0LL, 0LL, epi);
    }
}